// round 1
// baseline (speedup 1.0000x reference)
#include <cuda_runtime.h>
#include <cuda_bf16.h>
#include <cstdint>
#include <cstddef>
#include <math_constants.h>

// Problem constants (fixed by reference setup_inputs)
#define BB   2
#define SS   2048
#define TT   2048
#define DD   1024
#define HH   16
#define DH   64
#define BH   (BB*HH)                 // 32
#define ROWS (BB*SS)                 // 4096
#define OUT_ELEMS  ((size_t)BB*TT*DD)        // 4,194,304
#define ATTN_ELEMS ((size_t)BH*TT*SS)        // 134,217,728

// ---------------- scratch (static __device__ arrays: allocation-free) ------
__device__ float g_ln[3ull * OUT_ELEMS];     // qn,kn,vn  [3][B*S][D]
__device__ float g_proj[3ull * OUT_ELEMS];   // qs,ks,vs  [3][BH][S][64]
__device__ float g_ctx[OUT_ELEMS];           // attention context [B,T,D]
__device__ float g_attn[ATTN_ELEMS];         // fallback if d_out holds only `out`

// ---------------- helpers --------------------------------------------------
__device__ __forceinline__ uint32_t f2tf32(float x) {
    uint32_t r;
    asm("cvt.rna.tf32.f32 %0, %1;" : "=r"(r) : "f"(x));
    return r;
}

__device__ __forceinline__ void mma_tf32(float* c, const uint32_t* a, const uint32_t* b) {
    asm volatile(
        "mma.sync.aligned.m16n8k8.row.col.f32.tf32.tf32.f32 "
        "{%0,%1,%2,%3},{%4,%5,%6,%7},{%8,%9},{%0,%1,%2,%3};"
        : "+f"(c[0]), "+f"(c[1]), "+f"(c[2]), "+f"(c[3])
        : "r"(a[0]), "r"(a[1]), "r"(a[2]), "r"(a[3]), "r"(b[0]), "r"(b[1]));
}

// block reduction over 256 threads; ismax selects max vs sum
template <bool ISMAX>
__device__ __forceinline__ float block_reduce(float v) {
    __shared__ float sm[8];
    int tid = threadIdx.x;
#pragma unroll
    for (int o = 16; o; o >>= 1) {
        float other = __shfl_xor_sync(0xffffffffu, v, o);
        v = ISMAX ? fmaxf(v, other) : (v + other);
    }
    if ((tid & 31) == 0) sm[tid >> 5] = v;
    __syncthreads();
    if (tid < 32) {
        float r = (tid < 8) ? sm[tid] : (ISMAX ? -CUDART_INF_F : 0.0f);
#pragma unroll
        for (int o = 4; o; o >>= 1) {
            float other = __shfl_xor_sync(0xffffffffu, r, o);
            r = ISMAX ? fmaxf(r, other) : (r + other);
        }
        if (tid == 0) sm[0] = r;
    }
    __syncthreads();
    float res = sm[0];
    __syncthreads();   // make sm reusable by subsequent calls
    return res;
}

// ---------------- kernel 1: fused LayerNorm for q,k,v ----------------------
// grid: (B*S, 3), block: 256. Each block normalizes one 1024-elem row.
__global__ __launch_bounds__(256) void ln_kernel(
    const float* __restrict__ q, const float* __restrict__ k,
    const float* __restrict__ v, const float* __restrict__ gg,
    const float* __restrict__ bb, float* __restrict__ out)
{
    int row = blockIdx.x;
    int which = blockIdx.y;
    const float* x = (which == 0 ? q : (which == 1 ? k : v)) + (size_t)row * DD;
    float* o = out + (size_t)which * OUT_ELEMS + (size_t)row * DD;
    int tid = threadIdx.x;

    float4 xv = reinterpret_cast<const float4*>(x)[tid];
    float s = xv.x + xv.y + xv.z + xv.w;
    float mean = block_reduce<false>(s) * (1.0f / DD);
    float d0 = xv.x - mean, d1 = xv.y - mean, d2 = xv.z - mean, d3 = xv.w - mean;
    float ss = d0 * d0 + d1 * d1 + d2 * d2 + d3 * d3;
    float var = block_reduce<false>(ss) * (1.0f / DD);
    float rstd = rsqrtf(var + 1e-5f);

    float4 gv = reinterpret_cast<const float4*>(gg)[tid];
    float4 bv = reinterpret_cast<const float4*>(bb)[tid];
    float4 ov;
    ov.x = d0 * rstd * gv.x + bv.x;
    ov.y = d1 * rstd * gv.y + bv.y;
    ov.z = d2 * rstd * gv.z + bv.z;
    ov.w = d3 * rstd * gv.w + bv.w;
    reinterpret_cast<float4*>(o)[tid] = ov;
}

// ---------------- kernel 2: generic tf32 GEMM ------------------------------
// C = A[M,K](row-major) x B.  B_NK=true: B stored [N,K] row-major (i.e. X@W^T
// or Q@K^T).  B_NK=false: B stored [K,N] row-major (attn@V).
// EPI: 0=proj scatter to [BH,S,64] with (acc+bias)*scale
//      1=plain C[m*1024+n]=acc+bias
//      2=QK scores -> buf[z*T*S + m*S + n], causal block skip
//      3=PV -> ctx[(b*T+m)*D + h*64+n]
#define WARPS_M 2
#define WARPS_N 4
#define SMPAD 4

template <int BM, int BN, int BK, int EPI, bool B_NK>
__global__ __launch_bounds__(256) void gemm_k(
    const float* __restrict__ Ag, const float* __restrict__ Bg,
    const float* __restrict__ bias, float* __restrict__ Cg,
    int K, int lda, int ldb, long sA, long sB, float scale)
{
    const int m0 = blockIdx.y * BM;
    const int n0 = blockIdx.x * BN;
    const int z  = blockIdx.z;

    if (EPI == 2 && n0 >= m0 + BM) return;   // fully above causal diagonal

    const float* A = Ag + (long)z * sA;
    const float* B = Bg + (long)z * sB;

    constexpr int BKP = BK + SMPAD;
    constexpr int BR  = B_NK ? BN : BK;
    constexpr int BC  = B_NK ? BK : BN;
    constexpr int BCP = BC + SMPAD;
    __shared__ uint32_t As[BM][BKP];
    __shared__ uint32_t Bs[BR][BCP];

    const int tid  = threadIdx.x;
    const int lane = tid & 31;
    const int warp = tid >> 5;
    const int g  = lane >> 2;
    const int l4 = lane & 3;
    constexpr int WM = BM / WARPS_M;
    constexpr int WN = BN / WARPS_N;
    const int wm = warp & (WARPS_M - 1);
    const int wn = warp >> 1;
    const int wtm = wm * WM;
    const int wtn = wn * WN;
    constexpr int MF = WM / 16;
    constexpr int NF = WN / 8;

    float acc[MF][NF][4];
#pragma unroll
    for (int i = 0; i < MF; i++)
#pragma unroll
        for (int j = 0; j < NF; j++)
#pragma unroll
            for (int e = 0; e < 4; e++) acc[i][j][e] = 0.0f;

    int kend = K;
    if (EPI == 3) { int kb = m0 + BM; kend = kb < K ? kb : K; }

    for (int k0 = 0; k0 < kend; k0 += BK) {
        // ---- stage A tile (BM x BK), converting fp32 -> tf32 ----
        constexpr int AVEC = (BM * BK) / (256 * 4);
#pragma unroll
        for (int i = 0; i < AVEC; i++) {
            int idx = tid + i * 256;
            int r = idx / (BK / 4);
            int c = (idx % (BK / 4)) * 4;
            float4 v4 = *reinterpret_cast<const float4*>(
                &A[(size_t)(m0 + r) * lda + k0 + c]);
            As[r][c + 0] = f2tf32(v4.x);
            As[r][c + 1] = f2tf32(v4.y);
            As[r][c + 2] = f2tf32(v4.z);
            As[r][c + 3] = f2tf32(v4.w);
        }
        // ---- stage B tile ----
        constexpr int BVEC = (BR * BC) / (256 * 4);
#pragma unroll
        for (int i = 0; i < BVEC; i++) {
            int idx = tid + i * 256;
            int r = idx / (BC / 4);
            int c = (idx % (BC / 4)) * 4;
            float4 v4;
            if (B_NK)
                v4 = *reinterpret_cast<const float4*>(
                    &B[(size_t)(n0 + r) * ldb + k0 + c]);
            else
                v4 = *reinterpret_cast<const float4*>(
                    &B[(size_t)(k0 + r) * ldb + n0 + c]);
            Bs[r][c + 0] = f2tf32(v4.x);
            Bs[r][c + 1] = f2tf32(v4.y);
            Bs[r][c + 2] = f2tf32(v4.z);
            Bs[r][c + 3] = f2tf32(v4.w);
        }
        __syncthreads();

        // ---- compute ----
#pragma unroll
        for (int kk = 0; kk < BK; kk += 8) {
            uint32_t af[MF][4], bf[NF][2];
#pragma unroll
            for (int i = 0; i < MF; i++) {
                int r = wtm + i * 16 + g;
                af[i][0] = As[r][kk + l4];
                af[i][1] = As[r + 8][kk + l4];
                af[i][2] = As[r][kk + l4 + 4];
                af[i][3] = As[r + 8][kk + l4 + 4];
            }
#pragma unroll
            for (int j = 0; j < NF; j++) {
                int cN = wtn + j * 8 + g;
                if (B_NK) {
                    bf[j][0] = Bs[cN][kk + l4];
                    bf[j][1] = Bs[cN][kk + l4 + 4];
                } else {
                    bf[j][0] = Bs[kk + l4][cN];
                    bf[j][1] = Bs[kk + l4 + 4][cN];
                }
            }
#pragma unroll
            for (int i = 0; i < MF; i++)
#pragma unroll
                for (int j = 0; j < NF; j++)
                    mma_tf32(acc[i][j], af[i], bf[j]);
        }
        __syncthreads();
    }

    // ---- epilogue ----
    auto store = [&](int m, int n, float a) {
        if (EPI == 0) {
            float val = (a + bias[n]) * scale;
            int b = m >> 11, s = m & 2047, h = n >> 6, d = n & 63;
            Cg[((size_t)(b * HH + h) * SS + s) * DH + d] = val;
        } else if (EPI == 1) {
            Cg[(size_t)m * DD + n] = a + bias[n];
        } else if (EPI == 2) {
            Cg[(size_t)z * ((size_t)TT * SS) + (size_t)m * SS + n] = a;
        } else {
            int b = z >> 4, h = z & 15;
            Cg[((size_t)(b * TT + m)) * DD + h * DH + n] = a;
        }
    };
#pragma unroll
    for (int i = 0; i < MF; i++) {
#pragma unroll
        for (int j = 0; j < NF; j++) {
            int r  = m0 + wtm + i * 16 + g;
            int cB = n0 + wtn + j * 8 + l4 * 2;
            store(r,     cB,     acc[i][j][0]);
            store(r,     cB + 1, acc[i][j][1]);
            store(r + 8, cB,     acc[i][j][2]);
            store(r + 8, cB + 1, acc[i][j][3]);
        }
    }
}

// ---------------- kernel 3: causal softmax over score rows -----------------
// grid: (T, BH), block: 256.  Reads raw scores for s<=t, writes full attn row
// (zeros for s>t).
__global__ __launch_bounds__(256) void softmax_k(float* __restrict__ attn)
{
    int t = blockIdx.x;
    int z = blockIdx.y;
    float* row = attn + ((size_t)z * TT + t) * SS;
    int nv = t + 1;
    int tid = threadIdx.x;
    __shared__ float buf[SS];

    float m = -CUDART_INF_F;
    for (int i = tid; i < nv; i += 256) {
        float x = row[i];
        buf[i] = x;
        m = fmaxf(m, x);
    }
    m = block_reduce<true>(m);

    float s = 0.0f;
    for (int i = tid; i < nv; i += 256) {
        float e = __expf(buf[i] - m);
        buf[i] = e;
        s += e;
    }
    s = block_reduce<false>(s);
    float inv = 1.0f / s;

    for (int i = tid; i < SS / 4; i += 256) {
        int base = i * 4;
        float4 o;
        o.x = (base + 0 < nv) ? buf[base + 0] * inv : 0.0f;
        o.y = (base + 1 < nv) ? buf[base + 1] * inv : 0.0f;
        o.z = (base + 2 < nv) ? buf[base + 2] * inv : 0.0f;
        o.w = (base + 3 < nv) ? buf[base + 3] * inv : 0.0f;
        reinterpret_cast<float4*>(row)[i] = o;
    }
}

// ---------------- launch ---------------------------------------------------
extern "C" void kernel_launch(void* const* d_in, const int* in_sizes, int n_in,
                              void* d_out, int out_size)
{
    (void)in_sizes; (void)n_in;
    const float* q    = (const float*)d_in[0];
    const float* k    = (const float*)d_in[1];
    const float* v    = (const float*)d_in[2];
    const float* Wq   = (const float*)d_in[3];
    const float* bq   = (const float*)d_in[4];
    const float* Wk   = (const float*)d_in[5];
    const float* bk   = (const float*)d_in[6];
    const float* Wv   = (const float*)d_in[7];
    const float* bv   = (const float*)d_in[8];
    const float* Wo   = (const float*)d_in[9];
    const float* bo   = (const float*)d_in[10];
    const float* ln_g = (const float*)d_in[11];
    const float* ln_b = (const float*)d_in[12];

    float* ln_buf;  cudaGetSymbolAddress((void**)&ln_buf,  g_ln);
    float* pr_buf;  cudaGetSymbolAddress((void**)&pr_buf,  g_proj);
    float* ctx_buf; cudaGetSymbolAddress((void**)&ctx_buf, g_ctx);

    float* out = (float*)d_out;
    float* attn;
    if ((size_t)out_size >= OUT_ELEMS + ATTN_ELEMS) {
        attn = out + OUT_ELEMS;                       // tuple flattened (out, attn)
    } else {
        cudaGetSymbolAddress((void**)&attn, g_attn);  // attn not part of output
    }

    float* qn = ln_buf;
    float* kn = ln_buf + OUT_ELEMS;
    float* vn = ln_buf + 2 * OUT_ELEMS;
    float* qs = pr_buf;
    float* ks = pr_buf + OUT_ELEMS;
    float* vs = pr_buf + 2 * OUT_ELEMS;

    // 1. LayerNorm (all three inputs)
    ln_kernel<<<dim3(ROWS, 3), 256>>>(q, k, v, ln_g, ln_b, ln_buf);

    // 2. Projections (X @ W^T + b), scatter into [BH, S, 64]; q scaled 1/8
    gemm_k<128, 128, 32, 0, true><<<dim3(DD / 128, ROWS / 128, 1), 256>>>(
        qn, Wq, bq, qs, DD, DD, DD, 0, 0, 0.125f);
    gemm_k<128, 128, 32, 0, true><<<dim3(DD / 128, ROWS / 128, 1), 256>>>(
        kn, Wk, bk, ks, DD, DD, DD, 0, 0, 1.0f);
    gemm_k<128, 128, 32, 0, true><<<dim3(DD / 128, ROWS / 128, 1), 256>>>(
        vn, Wv, bv, vs, DD, DD, DD, 0, 0, 1.0f);

    // 3. QK^T batched over (b,h) with causal block skip -> raw scores
    gemm_k<128, 128, 32, 2, true><<<dim3(SS / 128, TT / 128, BH), 256>>>(
        qs, ks, nullptr, attn, DH, DH, DH,
        (long)SS * DH, (long)SS * DH, 1.0f);

    // 4. Causal softmax (writes exact attn incl. zero upper triangle)
    softmax_k<<<dim3(TT, BH), 256>>>(attn);

    // 5. attn @ V batched, causal K-bound -> ctx [B,T,D]
    gemm_k<128, 64, 32, 3, false><<<dim3(1, TT / 128, BH), 256>>>(
        attn, vs, nullptr, ctx_buf, SS, SS, DH,
        (long)TT * SS, (long)SS * DH, 1.0f);

    // 6. Output projection -> d_out[0 : B*T*D)
    gemm_k<128, 128, 32, 1, true><<<dim3(DD / 128, ROWS / 128, 1), 256>>>(
        ctx_buf, Wo, bo, out, DD, DD, DD, 0, 0, 1.0f);
}

// round 4
// speedup vs baseline: 1.3762x; 1.3762x over previous
#include <cuda_runtime.h>
#include <cuda_bf16.h>
#include <cstdint>
#include <cstddef>
#include <math_constants.h>

#define BB   2
#define SS   2048
#define DD   1024
#define HH   16
#define DH   64
#define BH   (BB*HH)                 // 32
#define ROWS (BB*SS)                 // 4096
#define OUT_ELEMS  ((size_t)BB*SS*DD)        // 4,194,304
#define ATTN_ELEMS ((size_t)BH*SS*SS)        // 134,217,728

// ---------------- scratch ---------------------------------------------------
__device__ float g_ln[3ull * OUT_ELEMS];     // qn,kn,vn
__device__ float g_pr[3ull * OUT_ELEMS];     // qs,ks,vs  [BH][S][64]
__device__ float g_ctx[OUT_ELEMS];           // context [B,T,D]
__device__ float g_sc[ATTN_ELEMS];           // exp(score) scratch
__device__ float g_part[(size_t)BH * SS * 16];   // per-block row partial sums
__device__ float g_inv[(size_t)BH * SS];         // 1/rowsum

// ---------------- helpers ---------------------------------------------------
__device__ __forceinline__ uint32_t f2tf32(float x) {
    uint32_t r;
    asm("cvt.rna.tf32.f32 %0, %1;" : "=r"(r) : "f"(x));
    return r;
}

__device__ __forceinline__ void mma_tf32(float* c, const uint32_t* a, const uint32_t* b) {
    asm volatile(
        "mma.sync.aligned.m16n8k8.row.col.f32.tf32.tf32.f32 "
        "{%0,%1,%2,%3},{%4,%5,%6,%7},{%8,%9},{%0,%1,%2,%3};"
        : "+f"(c[0]), "+f"(c[1]), "+f"(c[2]), "+f"(c[3])
        : "r"(a[0]), "r"(a[1]), "r"(a[2]), "r"(a[3]), "r"(b[0]), "r"(b[1]));
}

#define CP16(dst_u32, src_ptr) \
    asm volatile("cp.async.cg.shared.global [%0], [%1], 16;\n" :: "r"(dst_u32), "l"(src_ptr))
#define CPCOMMIT() asm volatile("cp.async.commit_group;\n" ::)
#define CPWAIT(n)  asm volatile("cp.async.wait_group %0;\n" :: "n"(n))

template <bool ISMAX>
__device__ __forceinline__ float block_reduce(float v) {
    __shared__ float sm[8];
    int tid = threadIdx.x;
#pragma unroll
    for (int o = 16; o; o >>= 1) {
        float other = __shfl_xor_sync(0xffffffffu, v, o);
        v = ISMAX ? fmaxf(v, other) : (v + other);
    }
    if ((tid & 31) == 0) sm[tid >> 5] = v;
    __syncthreads();
    if (tid < 32) {
        float r = (tid < 8) ? sm[tid] : (ISMAX ? -CUDART_INF_F : 0.0f);
#pragma unroll
        for (int o = 4; o; o >>= 1) {
            float other = __shfl_xor_sync(0xffffffffu, r, o);
            r = ISMAX ? fmaxf(r, other) : (r + other);
        }
        if (tid == 0) sm[0] = r;
    }
    __syncthreads();
    float res = sm[0];
    __syncthreads();
    return res;
}

// ---------------- kernel 1: LayerNorm ---------------------------------------
__global__ __launch_bounds__(256) void ln_kernel(
    const float* __restrict__ q, const float* __restrict__ k,
    const float* __restrict__ v, const float* __restrict__ gg,
    const float* __restrict__ bb, float* __restrict__ out)
{
    int row = blockIdx.x;
    int which = blockIdx.y;
    const float* x = (which == 0 ? q : (which == 1 ? k : v)) + (size_t)row * DD;
    float* o = out + (size_t)which * OUT_ELEMS + (size_t)row * DD;
    int tid = threadIdx.x;

    float4 xv = reinterpret_cast<const float4*>(x)[tid];
    float s = xv.x + xv.y + xv.z + xv.w;
    float mean = block_reduce<false>(s) * (1.0f / DD);
    float d0 = xv.x - mean, d1 = xv.y - mean, d2 = xv.z - mean, d3 = xv.w - mean;
    float ss = d0 * d0 + d1 * d1 + d2 * d2 + d3 * d3;
    float var = block_reduce<false>(ss) * (1.0f / DD);
    float rstd = rsqrtf(var + 1e-5f);

    float4 gv = reinterpret_cast<const float4*>(gg)[tid];
    float4 bv = reinterpret_cast<const float4*>(bb)[tid];
    float4 ov;
    ov.x = d0 * rstd * gv.x + bv.x;
    ov.y = d1 * rstd * gv.y + bv.y;
    ov.z = d2 * rstd * gv.z + bv.z;
    ov.w = d3 * rstd * gv.w + bv.w;
    reinterpret_cast<float4*>(o)[tid] = ov;
}

// ---------------- kernel 2: 128x128x32 tf32 GEMM, cp.async double buffer ----
// C = A[M,1024] x B[N,1024]^T.  EPI 0: proj scatter to [BH,S,64] (+bias)*scale
//                               EPI 1: C[m*1024+n] = acc + bias[n]
#define SA 40
template <int EPI>
__global__ __launch_bounds__(256, 2) void gemm2(
    const float* __restrict__ A, const float* __restrict__ Bm,
    const float* __restrict__ bias, float* __restrict__ C, float scale)
{
    extern __shared__ float smd[];
    float* As = smd;              // 2 x 128*40
    float* Bs = smd + 2 * 128 * SA;

    const int m0 = blockIdx.y * 128, n0 = blockIdx.x * 128;
    const int tid = threadIdx.x, lane = tid & 31, warp = tid >> 5;
    const int g = lane >> 2, l4 = lane & 3;
    const int wtm = (warp & 1) * 64, wtn = (warp >> 1) * 32;

    float acc[4][4][4];
#pragma unroll
    for (int i = 0; i < 4; i++)
#pragma unroll
        for (int j = 0; j < 4; j++)
#pragma unroll
            for (int e = 0; e < 4; e++) acc[i][j][e] = 0.0f;

    const int ar = tid >> 3;            // 0..31
    const int ac = (tid & 7) * 4;       // 0..28
    uint32_t sAu = (uint32_t)__cvta_generic_to_shared(As);
    uint32_t sBu = (uint32_t)__cvta_generic_to_shared(Bs);

    auto stage = [&](int chunk, int buf) {
        const float* Ap = A + (size_t)m0 * 1024 + chunk * 32;
        const float* Bp = Bm + (size_t)n0 * 1024 + chunk * 32;
        uint32_t da = sAu + (uint32_t)(buf * 128 * SA) * 4;
        uint32_t db = sBu + (uint32_t)(buf * 128 * SA) * 4;
#pragma unroll
        for (int i = 0; i < 4; i++) {
            int r = ar + i * 32;
            CP16(da + (uint32_t)(r * SA + ac) * 4, Ap + (size_t)r * 1024 + ac);
            CP16(db + (uint32_t)(r * SA + ac) * 4, Bp + (size_t)r * 1024 + ac);
        }
    };

    auto domma = [&](int buf) {
        const float* Ab = As + buf * 128 * SA;
        const float* Bb = Bs + buf * 128 * SA;
#pragma unroll
        for (int kk = 0; kk < 32; kk += 8) {
            int kc = kk + 2 * l4;
            uint32_t af[4][4], bf[4][2];
#pragma unroll
            for (int i = 0; i < 4; i++) {
                int r = wtm + i * 16 + g;
                float2 p0 = *(const float2*)&Ab[r * SA + kc];
                float2 p1 = *(const float2*)&Ab[(r + 8) * SA + kc];
                af[i][0] = f2tf32(p0.x); af[i][2] = f2tf32(p0.y);
                af[i][1] = f2tf32(p1.x); af[i][3] = f2tf32(p1.y);
            }
#pragma unroll
            for (int j = 0; j < 4; j++) {
                int cN = wtn + j * 8 + g;
                float2 p = *(const float2*)&Bb[cN * SA + kc];
                bf[j][0] = f2tf32(p.x); bf[j][1] = f2tf32(p.y);
            }
#pragma unroll
            for (int i = 0; i < 4; i++)
#pragma unroll
                for (int j = 0; j < 4; j++)
                    mma_tf32(acc[i][j], af[i], bf[j]);
        }
    };

    stage(0, 0); CPCOMMIT();
    int buf = 0;
    for (int c = 0; c < 32; c++) {
        if (c + 1 < 32) { stage(c + 1, buf ^ 1); CPCOMMIT(); CPWAIT(1); }
        else            { CPWAIT(0); }
        __syncthreads();
        domma(buf);
        __syncthreads();
        buf ^= 1;
    }

#pragma unroll
    for (int i = 0; i < 4; i++) {
        int m = m0 + wtm + i * 16 + g;
#pragma unroll
        for (int j = 0; j < 4; j++) {
            int n = n0 + wtn + j * 8 + 2 * l4;
            float2 bv = *(const float2*)&bias[n];
            float v0 = (acc[i][j][0] + bv.x) * scale;
            float v1 = (acc[i][j][1] + bv.y) * scale;
            float v2 = (acc[i][j][2] + bv.x) * scale;
            float v3 = (acc[i][j][3] + bv.y) * scale;
            if (EPI == 0) {
                int h = n >> 6, d = n & 63;
                size_t base0 = (((size_t)(m >> 11) * HH + h) * SS + (m & 2047)) * DH + d;
                size_t base1 = (((size_t)((m + 8) >> 11) * HH + h) * SS + ((m + 8) & 2047)) * DH + d;
                *(float2*)&C[base0] = make_float2(v0, v1);
                *(float2*)&C[base1] = make_float2(v2, v3);
            } else {
                *(float2*)&C[(size_t)m * DD + n] = make_float2(v0, v1);
                *(float2*)&C[(size_t)(m + 8) * DD + n] = make_float2(v2, v3);
            }
        }
    }
}

// ---------------- kernel 3: QK^T + exp + partial row sums -------------------
// grid (16,16,32). Lower blocks: exp(score) -> scratch, partial sums -> part.
// Upper blocks: zero-fill attn output.
#define SQ 72
__global__ __launch_bounds__(256, 2) void qk_kernel(
    const float* __restrict__ Q, const float* __restrict__ Kt,
    float* __restrict__ scratch, float* __restrict__ attnOut,
    float* __restrict__ part)
{
    const int n0 = blockIdx.x * 128, m0 = blockIdx.y * 128, z = blockIdx.z;
    const long zo = (long)z * SS;
    const int tid = threadIdx.x;

    if (n0 > m0) {                       // strictly above diagonal: zeros
        float4 zz = make_float4(0.f, 0.f, 0.f, 0.f);
#pragma unroll
        for (int t = 0; t < 16; t++) {
            int idx = tid + t * 256;
            int r = idx >> 5, c = (idx & 31) * 4;
            *(float4*)&attnOut[(zo + m0 + r) * SS + n0 + c] = zz;
        }
        return;
    }

    extern __shared__ float smd[];
    float* As = smd;                 // 128*72
    float* Bs = smd + 128 * SQ;

    const int lane = tid & 31, warp = tid >> 5;
    const int g = lane >> 2, l4 = lane & 3;
    const int wtm = (warp & 1) * 64, wtn = (warp >> 1) * 32, wn = warp >> 1;

    // stage Q,K tiles (raw f32)
#pragma unroll
    for (int t = 0; t < 8; t++) {
        int idx = tid + t * 256;
        int r = idx >> 4, c = (idx & 15) * 4;
        *(float4*)&As[r * SQ + c] = *(const float4*)&Q[(zo + m0 + r) * DH + c];
        *(float4*)&Bs[r * SQ + c] = *(const float4*)&Kt[(zo + n0 + r) * DH + c];
    }
    __syncthreads();

    float acc[4][4][4];
#pragma unroll
    for (int i = 0; i < 4; i++)
#pragma unroll
        for (int j = 0; j < 4; j++)
#pragma unroll
            for (int e = 0; e < 4; e++) acc[i][j][e] = 0.0f;

#pragma unroll
    for (int kk = 0; kk < 64; kk += 8) {
        int kc = kk + 2 * l4;
        uint32_t af[4][4], bf[4][2];
#pragma unroll
        for (int i = 0; i < 4; i++) {
            int r = wtm + i * 16 + g;
            float2 p0 = *(const float2*)&As[r * SQ + kc];
            float2 p1 = *(const float2*)&As[(r + 8) * SQ + kc];
            af[i][0] = f2tf32(p0.x); af[i][2] = f2tf32(p0.y);
            af[i][1] = f2tf32(p1.x); af[i][3] = f2tf32(p1.y);
        }
#pragma unroll
        for (int j = 0; j < 4; j++) {
            int cN = wtn + j * 8 + g;
            float2 p = *(const float2*)&Bs[cN * SQ + kc];
            bf[j][0] = f2tf32(p.x); bf[j][1] = f2tf32(p.y);
        }
#pragma unroll
        for (int i = 0; i < 4; i++)
#pragma unroll
            for (int j = 0; j < 4; j++)
                mma_tf32(acc[i][j], af[i], bf[j]);
    }

    // epilogue: exp + mask + store + partial row sums
    float rs[4][2];
#pragma unroll
    for (int i = 0; i < 4; i++) { rs[i][0] = 0.f; rs[i][1] = 0.f; }

#pragma unroll
    for (int i = 0; i < 4; i++) {
        int r0 = m0 + wtm + i * 16 + g;
#pragma unroll
        for (int j = 0; j < 4; j++) {
            int c0 = n0 + wtn + j * 8 + 2 * l4;
            float e0 = (c0     <= r0    ) ? __expf(acc[i][j][0]) : 0.f;
            float e1 = (c0 + 1 <= r0    ) ? __expf(acc[i][j][1]) : 0.f;
            float e2 = (c0     <= r0 + 8) ? __expf(acc[i][j][2]) : 0.f;
            float e3 = (c0 + 1 <= r0 + 8) ? __expf(acc[i][j][3]) : 0.f;
            *(float2*)&scratch[(zo + r0) * SS + c0]       = make_float2(e0, e1);
            *(float2*)&scratch[(zo + r0 + 8) * SS + c0]   = make_float2(e2, e3);
            rs[i][0] += e0 + e1;
            rs[i][1] += e2 + e3;
        }
    }
    // quad-reduce over l4
#pragma unroll
    for (int i = 0; i < 4; i++)
#pragma unroll
        for (int h = 0; h < 2; h++) {
            float v = rs[i][h];
            v += __shfl_xor_sync(0xffffffffu, v, 1);
            v += __shfl_xor_sync(0xffffffffu, v, 2);
            rs[i][h] = v;
        }
    __syncthreads();                 // done reading As/Bs -> reuse as reduce buf
    float* red = smd;                // [128][4]
    if (l4 == 0) {
#pragma unroll
        for (int i = 0; i < 4; i++) {
            red[(wtm + i * 16 + g) * 4 + wn]     = rs[i][0];
            red[(wtm + i * 16 + g + 8) * 4 + wn] = rs[i][1];
        }
    }
    __syncthreads();
    if (tid < 128) {
        float s = red[tid * 4] + red[tid * 4 + 1] + red[tid * 4 + 2] + red[tid * 4 + 3];
        part[(zo + m0 + tid) * 16 + (n0 >> 7)] = s;
    }
}

// ---------------- kernel 4: row-sum reduce -> reciprocal --------------------
__global__ __launch_bounds__(256) void rowsum_kernel(
    const float* __restrict__ part, float* __restrict__ inv)
{
    int idx = blockIdx.x * 256 + threadIdx.x;    // < 65536
    int t = idx & (SS - 1);
    int nb = (t >> 7) + 1;
    float s = 0.f;
    for (int b = 0; b < nb; b++) s += part[(size_t)idx * 16 + b];
    inv[idx] = 1.0f / s;
}

// ---------------- kernel 5: PV GEMM, normalize + write attn -----------------
// grid (16, 32): x = m-block, y = z.  BM=128, BN=64, BK=32.
#define SPA 40
__global__ __launch_bounds__(256, 2) void pv_kernel(
    float* __restrict__ scratch, const float* __restrict__ V,
    const float* __restrict__ inv, float* __restrict__ attnOut,
    float* __restrict__ ctx)
{
    const int m0 = blockIdx.x * 128, z = blockIdx.y;
    const long zo = (long)z * SS;
    const int tid = threadIdx.x, lane = tid & 31, warp = tid >> 5;
    const int g = lane >> 2, l4 = lane & 3;
    const int wtm = (warp & 1) * 64, wtn = (warp >> 1) * 16;

    extern __shared__ float smd[];
    float* As = smd;                           // 2 x 128*40
    float* Bs = smd + 2 * 128 * SPA;           // 2 x 32*64
    float* invs = Bs + 2 * 32 * 64;            // 128

    if (tid < 128) invs[tid] = inv[zo + m0 + tid];
    __syncthreads();

    float acc[4][2][4];
#pragma unroll
    for (int i = 0; i < 4; i++)
#pragma unroll
        for (int j = 0; j < 2; j++)
#pragma unroll
            for (int e = 0; e < 4; e++) acc[i][j][e] = 0.0f;

    const int NC = (m0 >> 5) + 4;

    float4 pa[4]; float4 pb[2];
    int arr[4], acl[4];
#pragma unroll
    for (int t = 0; t < 4; t++) { int idx = tid + t * 256; arr[t] = idx >> 3; acl[t] = (idx & 7) * 4; }
    int bkr[2], bnc[2];
#pragma unroll
    for (int t = 0; t < 2; t++) { int idx = tid + t * 256; bkr[t] = idx >> 4; bnc[t] = (idx & 15) * 4; }

    auto loadc = [&](int c) {
        int k0 = c * 32;
#pragma unroll
        for (int t = 0; t < 4; t++)
            pa[t] = *(const float4*)&scratch[(zo + m0 + arr[t]) * SS + k0 + acl[t]];
#pragma unroll
        for (int t = 0; t < 2; t++)
            pb[t] = *(const float4*)&V[(zo + k0 + bkr[t]) * DH + bnc[t]];
    };

    loadc(0);
    for (int c = 0; c < NC; c++) {
        int buf = c & 1;
        float* Ab = As + buf * 128 * SPA;
        float* Bb = Bs + buf * 32 * 64;
        int k0 = c * 32;
        // normalize, write attn, store smem
#pragma unroll
        for (int t = 0; t < 4; t++) {
            float iv = invs[arr[t]];
            float4 v = pa[t];
            v.x *= iv; v.y *= iv; v.z *= iv; v.w *= iv;
            *(float4*)&attnOut[(zo + m0 + arr[t]) * SS + k0 + acl[t]] = v;
            *(float4*)&Ab[arr[t] * SPA + acl[t]] = v;
        }
#pragma unroll
        for (int t = 0; t < 2; t++) {
            int cp = (bnc[t] + 4 * bkr[t]) & 63;      // rotate-4 swizzle
            *(float4*)&Bb[bkr[t] * 64 + cp] = pb[t];
        }
        __syncthreads();
        if (c + 1 < NC) loadc(c + 1);
        // MMA over current buffer
#pragma unroll
        for (int kk = 0; kk < 32; kk += 8) {
            int kc = kk + 2 * l4;
            uint32_t af[4][4], bf[2][2];
#pragma unroll
            for (int i = 0; i < 4; i++) {
                int r = wtm + i * 16 + g;
                float2 p0 = *(const float2*)&Ab[r * SPA + kc];
                float2 p1 = *(const float2*)&Ab[(r + 8) * SPA + kc];
                af[i][0] = f2tf32(p0.x); af[i][2] = f2tf32(p0.y);
                af[i][1] = f2tf32(p1.x); af[i][3] = f2tf32(p1.y);
            }
#pragma unroll
            for (int j = 0; j < 2; j++) {
                int cN = wtn + j * 8 + g;
                bf[j][0] = f2tf32(Bb[kc * 64 + ((cN + 4 * kc) & 63)]);
                bf[j][1] = f2tf32(Bb[(kc + 1) * 64 + ((cN + 4 * (kc + 1)) & 63)]);
            }
#pragma unroll
            for (int i = 0; i < 4; i++)
#pragma unroll
                for (int j = 0; j < 2; j++)
                    mma_tf32(acc[i][j], af[i], bf[j]);
        }
        __syncthreads();
    }

    // epilogue -> ctx [B,T,D]
    const int b = z >> 4, h = z & 15;
#pragma unroll
    for (int i = 0; i < 4; i++) {
        int r0 = m0 + wtm + i * 16 + g;
#pragma unroll
        for (int j = 0; j < 2; j++) {
            int c0 = wtn + j * 8 + 2 * l4;
            size_t ob = ((size_t)b * SS + r0) * DD + h * DH + c0;
            *(float2*)&ctx[ob]            = make_float2(acc[i][j][0], acc[i][j][1]);
            *(float2*)&ctx[ob + 8 * DD]   = make_float2(acc[i][j][2], acc[i][j][3]);
        }
    }
}

// ---------------- launch -----------------------------------------------------
extern "C" void kernel_launch(void* const* d_in, const int* in_sizes, int n_in,
                              void* d_out, int out_size)
{
    (void)in_sizes; (void)n_in;
    const float* q    = (const float*)d_in[0];
    const float* k    = (const float*)d_in[1];
    const float* v    = (const float*)d_in[2];
    const float* Wq   = (const float*)d_in[3];
    const float* bq   = (const float*)d_in[4];
    const float* Wk   = (const float*)d_in[5];
    const float* bk   = (const float*)d_in[6];
    const float* Wv   = (const float*)d_in[7];
    const float* bv   = (const float*)d_in[8];
    const float* Wo   = (const float*)d_in[9];
    const float* bo   = (const float*)d_in[10];
    const float* ln_g = (const float*)d_in[11];
    const float* ln_b = (const float*)d_in[12];

    float *ln_buf, *pr_buf, *ctx_buf, *sc_buf, *part_buf, *inv_buf;
    cudaGetSymbolAddress((void**)&ln_buf,   g_ln);
    cudaGetSymbolAddress((void**)&pr_buf,   g_pr);
    cudaGetSymbolAddress((void**)&ctx_buf,  g_ctx);
    cudaGetSymbolAddress((void**)&sc_buf,   g_sc);
    cudaGetSymbolAddress((void**)&part_buf, g_part);
    cudaGetSymbolAddress((void**)&inv_buf,  g_inv);

    float* out = (float*)d_out;
    float* attnOut = ((size_t)out_size >= OUT_ELEMS + ATTN_ELEMS)
                        ? out + OUT_ELEMS
                        : sc_buf;   // fallback: normalize in place

    float* qn = ln_buf;
    float* kn = ln_buf + OUT_ELEMS;
    float* vn = ln_buf + 2 * OUT_ELEMS;
    float* qs = pr_buf;
    float* ks = pr_buf + OUT_ELEMS;
    float* vs = pr_buf + 2 * OUT_ELEMS;

    // Idempotent, called every launch (no static guards per harness rules)
    cudaFuncSetAttribute(gemm2<0>, cudaFuncAttributeMaxDynamicSharedMemorySize, 4 * 128 * SA * 4);
    cudaFuncSetAttribute(gemm2<1>, cudaFuncAttributeMaxDynamicSharedMemorySize, 4 * 128 * SA * 4);
    cudaFuncSetAttribute(qk_kernel, cudaFuncAttributeMaxDynamicSharedMemorySize, 2 * 128 * SQ * 4);
    cudaFuncSetAttribute(pv_kernel, cudaFuncAttributeMaxDynamicSharedMemorySize,
                         (2 * 128 * SPA + 2 * 32 * 64 + 128) * 4);

    // 1. LayerNorm
    ln_kernel<<<dim3(ROWS, 3), 256>>>(q, k, v, ln_g, ln_b, ln_buf);

    // 2. Projections
    size_t gsm = 4 * 128 * SA * 4;
    gemm2<0><<<dim3(8, 32), 256, gsm>>>(qn, Wq, bq, qs, 0.125f);
    gemm2<0><<<dim3(8, 32), 256, gsm>>>(kn, Wk, bk, ks, 1.0f);
    gemm2<0><<<dim3(8, 32), 256, gsm>>>(vn, Wv, bv, vs, 1.0f);

    // 3. QK^T + exp + partial sums (+ zero-fill upper attn)
    qk_kernel<<<dim3(16, 16, 32), 256, 2 * 128 * SQ * 4>>>(qs, ks, sc_buf, attnOut, part_buf);

    // 4. Row sums -> reciprocals
    rowsum_kernel<<<256, 256>>>(part_buf, inv_buf);

    // 5. PV + normalize + write attn
    pv_kernel<<<dim3(16, 32), 256, (2 * 128 * SPA + 2 * 32 * 64 + 128) * 4>>>(
        sc_buf, vs, inv_buf, attnOut, ctx_buf);

    // 6. Output projection
    gemm2<1><<<dim3(8, 32), 256, gsm>>>(ctx_buf, Wo, bo, out, 1.0f);
}

// round 7
// speedup vs baseline: 1.4946x; 1.0860x over previous
#include <cuda_runtime.h>
#include <cuda_bf16.h>
#include <cstdint>
#include <cstddef>
#include <math_constants.h>

#define BB   2
#define SS   2048
#define DD   1024
#define HH   16
#define DH   64
#define BH   (BB*HH)                 // 32
#define ROWS (BB*SS)                 // 4096
#define OUT_ELEMS  ((size_t)BB*SS*DD)        // 4,194,304
#define ATTN_ELEMS ((size_t)BH*SS*SS)        // 134,217,728

// ---------------- scratch ---------------------------------------------------
__device__ float g_ln[3ull * OUT_ELEMS];     // qn,kn,vn (tf32-rounded)
__device__ float g_pr[3ull * OUT_ELEMS];     // qs,ks,vs (tf32-rounded) [BH][S][64]
__device__ float g_ctx[OUT_ELEMS];           // context [B,T,D] (tf32-rounded)
__device__ float g_sc[ATTN_ELEMS];           // exp(score) scratch (exact fp32)
__device__ float g_wt[4ull * DD * DD];       // tf32-rounded Wq,Wk,Wv,Wo
__device__ float g_part[(size_t)BH * SS * 16];   // per-block row partial sums
__device__ float g_inv[(size_t)BH * SS];         // 1/rowsum

// ---------------- helpers ---------------------------------------------------
__device__ __forceinline__ uint32_t f2tf32(float x) {
    uint32_t r;
    asm("cvt.rna.tf32.f32 %0, %1;" : "=r"(r) : "f"(x));
    return r;
}
__device__ __forceinline__ float rtf(float x) { return __uint_as_float(f2tf32(x)); }

__device__ __forceinline__ void mma_tf32(float* c, const uint32_t* a, const uint32_t* b) {
    asm volatile(
        "mma.sync.aligned.m16n8k8.row.col.f32.tf32.tf32.f32 "
        "{%0,%1,%2,%3},{%4,%5,%6,%7},{%8,%9},{%0,%1,%2,%3};"
        : "+f"(c[0]), "+f"(c[1]), "+f"(c[2]), "+f"(c[3])
        : "r"(a[0]), "r"(a[1]), "r"(a[2]), "r"(a[3]), "r"(b[0]), "r"(b[1]));
}

#define CP16(dst_u32, src_ptr) \
    asm volatile("cp.async.cg.shared.global [%0], [%1], 16;\n" :: "r"(dst_u32), "l"(src_ptr))
#define CPCOMMIT() asm volatile("cp.async.commit_group;\n" ::)
#define CPWAIT(n)  asm volatile("cp.async.wait_group %0;\n" :: "n"(n))

template <bool ISMAX>
__device__ __forceinline__ float block_reduce(float v) {
    __shared__ float sm[8];
    int tid = threadIdx.x;
#pragma unroll
    for (int o = 16; o; o >>= 1) {
        float other = __shfl_xor_sync(0xffffffffu, v, o);
        v = ISMAX ? fmaxf(v, other) : (v + other);
    }
    if ((tid & 31) == 0) sm[tid >> 5] = v;
    __syncthreads();
    if (tid < 32) {
        float r = (tid < 8) ? sm[tid] : (ISMAX ? -CUDART_INF_F : 0.0f);
#pragma unroll
        for (int o = 4; o; o >>= 1) {
            float other = __shfl_xor_sync(0xffffffffu, r, o);
            r = ISMAX ? fmaxf(r, other) : (r + other);
        }
        if (tid == 0) sm[0] = r;
    }
    __syncthreads();
    float res = sm[0];
    __syncthreads();
    return res;
}

// ---------------- kernel 0: round weights to tf32 ---------------------------
__global__ __launch_bounds__(256) void roundw_kernel(
    const float4* __restrict__ in, float4* __restrict__ out)
{
    int idx = blockIdx.x * 256 + threadIdx.x;    // DD*DD/4 threads
    float4 v = in[idx];
    v.x = rtf(v.x); v.y = rtf(v.y); v.z = rtf(v.z); v.w = rtf(v.w);
    out[idx] = v;
}

// ---------------- kernel 1: LayerNorm (tf32-rounded output) -----------------
__global__ __launch_bounds__(256) void ln_kernel(
    const float* __restrict__ q, const float* __restrict__ k,
    const float* __restrict__ v, const float* __restrict__ gg,
    const float* __restrict__ bb, float* __restrict__ out)
{
    int row = blockIdx.x;
    int which = blockIdx.y;
    const float* x = (which == 0 ? q : (which == 1 ? k : v)) + (size_t)row * DD;
    float* o = out + (size_t)which * OUT_ELEMS + (size_t)row * DD;
    int tid = threadIdx.x;

    float4 xv = reinterpret_cast<const float4*>(x)[tid];
    float s = xv.x + xv.y + xv.z + xv.w;
    float mean = block_reduce<false>(s) * (1.0f / DD);
    float d0 = xv.x - mean, d1 = xv.y - mean, d2 = xv.z - mean, d3 = xv.w - mean;
    float ss = d0 * d0 + d1 * d1 + d2 * d2 + d3 * d3;
    float var = block_reduce<false>(ss) * (1.0f / DD);
    float rstd = rsqrtf(var + 1e-5f);

    float4 gv = reinterpret_cast<const float4*>(gg)[tid];
    float4 bv = reinterpret_cast<const float4*>(bb)[tid];
    float4 ov;
    ov.x = rtf(d0 * rstd * gv.x + bv.x);
    ov.y = rtf(d1 * rstd * gv.y + bv.y);
    ov.z = rtf(d2 * rstd * gv.z + bv.z);
    ov.w = rtf(d3 * rstd * gv.w + bv.w);
    reinterpret_cast<float4*>(o)[tid] = ov;
}

// ---------------- kernel 2: 128x128x32 tf32 GEMM, cp.async double buffer ----
// Inputs are PRE-ROUNDED tf32 bit patterns: inner loop has zero cvt.
// EPI 0: proj scatter to [BH,S,64], value tf32-rounded (feeds later MMAs)
// EPI 1: plain C[m*1024+n] = acc + bias[n] (exact, final output)
#define SA 40
template <int EPI>
__global__ __launch_bounds__(256, 2) void gemm2(
    const float* __restrict__ A, const float* __restrict__ Bm,
    const float* __restrict__ bias, float* __restrict__ C, float scale)
{
    extern __shared__ float smd[];
    float* As = smd;              // 2 x 128*40
    float* Bs = smd + 2 * 128 * SA;

    const int m0 = blockIdx.y * 128, n0 = blockIdx.x * 128;
    const int tid = threadIdx.x, lane = tid & 31, warp = tid >> 5;
    const int g = lane >> 2, l4 = lane & 3;
    const int wtm = (warp & 1) * 64, wtn = (warp >> 1) * 32;

    float acc[4][4][4];
#pragma unroll
    for (int i = 0; i < 4; i++)
#pragma unroll
        for (int j = 0; j < 4; j++)
#pragma unroll
            for (int e = 0; e < 4; e++) acc[i][j][e] = 0.0f;

    const int ar = tid >> 3;            // 0..31
    const int ac = (tid & 7) * 4;       // 0..28
    uint32_t sAu = (uint32_t)__cvta_generic_to_shared(As);
    uint32_t sBu = (uint32_t)__cvta_generic_to_shared(Bs);

    auto stage = [&](int chunk, int buf) {
        const float* Ap = A + (size_t)m0 * 1024 + chunk * 32;
        const float* Bp = Bm + (size_t)n0 * 1024 + chunk * 32;
        uint32_t da = sAu + (uint32_t)(buf * 128 * SA) * 4;
        uint32_t db = sBu + (uint32_t)(buf * 128 * SA) * 4;
#pragma unroll
        for (int i = 0; i < 4; i++) {
            int r = ar + i * 32;
            CP16(da + (uint32_t)(r * SA + ac) * 4, Ap + (size_t)r * 1024 + ac);
            CP16(db + (uint32_t)(r * SA + ac) * 4, Bp + (size_t)r * 1024 + ac);
        }
    };

    auto domma = [&](int buf) {
        const float* Ab = As + buf * 128 * SA;
        const float* Bb = Bs + buf * 128 * SA;
#pragma unroll
        for (int kk = 0; kk < 32; kk += 8) {
            int kc = kk + 2 * l4;
            uint32_t af[4][4], bf[4][2];
#pragma unroll
            for (int i = 0; i < 4; i++) {
                int r = wtm + i * 16 + g;
                uint2 p0 = *(const uint2*)&Ab[r * SA + kc];
                uint2 p1 = *(const uint2*)&Ab[(r + 8) * SA + kc];
                af[i][0] = p0.x; af[i][2] = p0.y;
                af[i][1] = p1.x; af[i][3] = p1.y;
            }
#pragma unroll
            for (int j = 0; j < 4; j++) {
                int cN = wtn + j * 8 + g;
                uint2 p = *(const uint2*)&Bb[cN * SA + kc];
                bf[j][0] = p.x; bf[j][1] = p.y;
            }
#pragma unroll
            for (int i = 0; i < 4; i++)
#pragma unroll
                for (int j = 0; j < 4; j++)
                    mma_tf32(acc[i][j], af[i], bf[j]);
        }
    };

    stage(0, 0); CPCOMMIT();
    int buf = 0;
    for (int c = 0; c < 32; c++) {
        if (c + 1 < 32) { stage(c + 1, buf ^ 1); CPCOMMIT(); CPWAIT(1); }
        else            { CPWAIT(0); }
        __syncthreads();
        domma(buf);
        __syncthreads();
        buf ^= 1;
    }

#pragma unroll
    for (int i = 0; i < 4; i++) {
        int m = m0 + wtm + i * 16 + g;
#pragma unroll
        for (int j = 0; j < 4; j++) {
            int n = n0 + wtn + j * 8 + 2 * l4;
            float2 bv = *(const float2*)&bias[n];
            float v0 = (acc[i][j][0] + bv.x) * scale;
            float v1 = (acc[i][j][1] + bv.y) * scale;
            float v2 = (acc[i][j][2] + bv.x) * scale;
            float v3 = (acc[i][j][3] + bv.y) * scale;
            if (EPI == 0) {
                v0 = rtf(v0); v1 = rtf(v1); v2 = rtf(v2); v3 = rtf(v3);
                int h = n >> 6, d = n & 63;
                size_t base0 = (((size_t)(m >> 11) * HH + h) * SS + (m & 2047)) * DH + d;
                size_t base1 = (((size_t)((m + 8) >> 11) * HH + h) * SS + ((m + 8) & 2047)) * DH + d;
                *(float2*)&C[base0] = make_float2(v0, v1);
                *(float2*)&C[base1] = make_float2(v2, v3);
            } else {
                *(float2*)&C[(size_t)m * DD + n] = make_float2(v0, v1);
                *(float2*)&C[(size_t)(m + 8) * DD + n] = make_float2(v2, v3);
            }
        }
    }
}

// ---------------- kernel 3: QK^T + exp + partial row sums -------------------
// Inputs pre-rounded tf32: no cvt in compute.
#define SQ 72
__global__ __launch_bounds__(256, 2) void qk_kernel(
    const float* __restrict__ Q, const float* __restrict__ Kt,
    float* __restrict__ scratch, float* __restrict__ attnOut,
    float* __restrict__ part)
{
    const int n0 = blockIdx.x * 128, m0 = blockIdx.y * 128, z = blockIdx.z;
    const long zo = (long)z * SS;
    const int tid = threadIdx.x;

    if (n0 > m0) {                       // strictly above diagonal: zeros
        float4 zz = make_float4(0.f, 0.f, 0.f, 0.f);
#pragma unroll
        for (int t = 0; t < 16; t++) {
            int idx = tid + t * 256;
            int r = idx >> 5, c = (idx & 31) * 4;
            *(float4*)&attnOut[(zo + m0 + r) * SS + n0 + c] = zz;
        }
        return;
    }

    extern __shared__ float smd[];
    float* As = smd;                 // 128*72
    float* Bs = smd + 128 * SQ;

    const int lane = tid & 31, warp = tid >> 5;
    const int g = lane >> 2, l4 = lane & 3;
    const int wtm = (warp & 1) * 64, wtn = (warp >> 1) * 32, wn = warp >> 1;

#pragma unroll
    for (int t = 0; t < 8; t++) {
        int idx = tid + t * 256;
        int r = idx >> 4, c = (idx & 15) * 4;
        *(float4*)&As[r * SQ + c] = *(const float4*)&Q[(zo + m0 + r) * DH + c];
        *(float4*)&Bs[r * SQ + c] = *(const float4*)&Kt[(zo + n0 + r) * DH + c];
    }
    __syncthreads();

    float acc[4][4][4];
#pragma unroll
    for (int i = 0; i < 4; i++)
#pragma unroll
        for (int j = 0; j < 4; j++)
#pragma unroll
            for (int e = 0; e < 4; e++) acc[i][j][e] = 0.0f;

#pragma unroll
    for (int kk = 0; kk < 64; kk += 8) {
        int kc = kk + 2 * l4;
        uint32_t af[4][4], bf[4][2];
#pragma unroll
        for (int i = 0; i < 4; i++) {
            int r = wtm + i * 16 + g;
            uint2 p0 = *(const uint2*)&As[r * SQ + kc];
            uint2 p1 = *(const uint2*)&As[(r + 8) * SQ + kc];
            af[i][0] = p0.x; af[i][2] = p0.y;
            af[i][1] = p1.x; af[i][3] = p1.y;
        }
#pragma unroll
        for (int j = 0; j < 4; j++) {
            int cN = wtn + j * 8 + g;
            uint2 p = *(const uint2*)&Bs[cN * SQ + kc];
            bf[j][0] = p.x; bf[j][1] = p.y;
        }
#pragma unroll
        for (int i = 0; i < 4; i++)
#pragma unroll
            for (int j = 0; j < 4; j++)
                mma_tf32(acc[i][j], af[i], bf[j]);
    }

    // epilogue: exp + mask + store + partial row sums
    float rs[4][2];
#pragma unroll
    for (int i = 0; i < 4; i++) { rs[i][0] = 0.f; rs[i][1] = 0.f; }

#pragma unroll
    for (int i = 0; i < 4; i++) {
        int r0 = m0 + wtm + i * 16 + g;
#pragma unroll
        for (int j = 0; j < 4; j++) {
            int c0 = n0 + wtn + j * 8 + 2 * l4;
            float e0 = (c0     <= r0    ) ? __expf(acc[i][j][0]) : 0.f;
            float e1 = (c0 + 1 <= r0    ) ? __expf(acc[i][j][1]) : 0.f;
            float e2 = (c0     <= r0 + 8) ? __expf(acc[i][j][2]) : 0.f;
            float e3 = (c0 + 1 <= r0 + 8) ? __expf(acc[i][j][3]) : 0.f;
            *(float2*)&scratch[(zo + r0) * SS + c0]       = make_float2(e0, e1);
            *(float2*)&scratch[(zo + r0 + 8) * SS + c0]   = make_float2(e2, e3);
            rs[i][0] += e0 + e1;
            rs[i][1] += e2 + e3;
        }
    }
#pragma unroll
    for (int i = 0; i < 4; i++)
#pragma unroll
        for (int h = 0; h < 2; h++) {
            float v = rs[i][h];
            v += __shfl_xor_sync(0xffffffffu, v, 1);
            v += __shfl_xor_sync(0xffffffffu, v, 2);
            rs[i][h] = v;
        }
    __syncthreads();
    float* red = smd;                // [128][4]
    if (l4 == 0) {
#pragma unroll
        for (int i = 0; i < 4; i++) {
            red[(wtm + i * 16 + g) * 4 + wn]     = rs[i][0];
            red[(wtm + i * 16 + g + 8) * 4 + wn] = rs[i][1];
        }
    }
    __syncthreads();
    if (tid < 128) {
        float s = red[tid * 4] + red[tid * 4 + 1] + red[tid * 4 + 2] + red[tid * 4 + 3];
        part[(zo + m0 + tid) * 16 + (n0 >> 7)] = s;
    }
}

// ---------------- kernel 4: row-sum reduce -> reciprocal --------------------
__global__ __launch_bounds__(256) void rowsum_kernel(
    const float* __restrict__ part, float* __restrict__ inv)
{
    int idx = blockIdx.x * 256 + threadIdx.x;    // < 65536
    int t = idx & (SS - 1);
    int nb = (t >> 7) + 1;
    float s = 0.f;
    for (int b = 0; b < nb; b++) s += part[(size_t)idx * 16 + b];
    inv[idx] = 1.0f / s;
}

// ---------------- kernel 5: PV GEMM, normalize + write attn -----------------
#define SPA 40
__global__ __launch_bounds__(256, 2) void pv_kernel(
    float* __restrict__ scratch, const float* __restrict__ V,
    const float* __restrict__ inv, float* __restrict__ attnOut,
    float* __restrict__ ctx)
{
    const int m0 = blockIdx.x * 128, z = blockIdx.y;
    const long zo = (long)z * SS;
    const int tid = threadIdx.x, lane = tid & 31, warp = tid >> 5;
    const int g = lane >> 2, l4 = lane & 3;
    const int wtm = (warp & 1) * 64, wtn = (warp >> 1) * 16;

    extern __shared__ float smd[];
    float* As = smd;                           // 2 x 128*40
    float* Bs = smd + 2 * 128 * SPA;           // 2 x 32*64
    float* invs = Bs + 2 * 32 * 64;            // 128

    if (tid < 128) invs[tid] = inv[zo + m0 + tid];
    __syncthreads();

    float acc[4][2][4];
#pragma unroll
    for (int i = 0; i < 4; i++)
#pragma unroll
        for (int j = 0; j < 2; j++)
#pragma unroll
            for (int e = 0; e < 4; e++) acc[i][j][e] = 0.0f;

    const int NC = (m0 >> 5) + 4;

    float4 pa[4]; float4 pb[2];
    int arr[4], acl[4];
#pragma unroll
    for (int t = 0; t < 4; t++) { int idx = tid + t * 256; arr[t] = idx >> 3; acl[t] = (idx & 7) * 4; }
    int bkr[2], bnc[2];
#pragma unroll
    for (int t = 0; t < 2; t++) { int idx = tid + t * 256; bkr[t] = idx >> 4; bnc[t] = (idx & 15) * 4; }

    auto loadc = [&](int c) {
        int k0 = c * 32;
#pragma unroll
        for (int t = 0; t < 4; t++)
            pa[t] = *(const float4*)&scratch[(zo + m0 + arr[t]) * SS + k0 + acl[t]];
#pragma unroll
        for (int t = 0; t < 2; t++)
            pb[t] = *(const float4*)&V[(zo + k0 + bkr[t]) * DH + bnc[t]];
    };

    loadc(0);
    for (int c = 0; c < NC; c++) {
        int buf = c & 1;
        float* Ab = As + buf * 128 * SPA;
        float* Bb = Bs + buf * 32 * 64;
        int k0 = c * 32;
        // normalize: exact -> attn output, tf32-rounded -> smem MMA operand
#pragma unroll
        for (int t = 0; t < 4; t++) {
            float iv = invs[arr[t]];
            float4 v = pa[t];
            v.x *= iv; v.y *= iv; v.z *= iv; v.w *= iv;
            *(float4*)&attnOut[(zo + m0 + arr[t]) * SS + k0 + acl[t]] = v;
            float4 vr;
            vr.x = rtf(v.x); vr.y = rtf(v.y); vr.z = rtf(v.z); vr.w = rtf(v.w);
            *(float4*)&Ab[arr[t] * SPA + acl[t]] = vr;
        }
#pragma unroll
        for (int t = 0; t < 2; t++) {
            int cp = (bnc[t] + 4 * bkr[t]) & 63;      // rotate-4 swizzle
            *(float4*)&Bb[bkr[t] * 64 + cp] = pb[t];  // V pre-rounded
        }
        __syncthreads();
        if (c + 1 < NC) loadc(c + 1);
#pragma unroll
        for (int kk = 0; kk < 32; kk += 8) {
            int kc = kk + 2 * l4;
            uint32_t af[4][4], bf[2][2];
#pragma unroll
            for (int i = 0; i < 4; i++) {
                int r = wtm + i * 16 + g;
                uint2 p0 = *(const uint2*)&Ab[r * SPA + kc];
                uint2 p1 = *(const uint2*)&Ab[(r + 8) * SPA + kc];
                af[i][0] = p0.x; af[i][2] = p0.y;
                af[i][1] = p1.x; af[i][3] = p1.y;
            }
#pragma unroll
            for (int j = 0; j < 2; j++) {
                int cN = wtn + j * 8 + g;
                bf[j][0] = __float_as_uint(Bb[kc * 64 + ((cN + 4 * kc) & 63)]);
                bf[j][1] = __float_as_uint(Bb[(kc + 1) * 64 + ((cN + 4 * (kc + 1)) & 63)]);
            }
#pragma unroll
            for (int i = 0; i < 4; i++)
#pragma unroll
                for (int j = 0; j < 2; j++)
                    mma_tf32(acc[i][j], af[i], bf[j]);
        }
        __syncthreads();
    }

    // epilogue -> ctx [B,T,D], tf32-rounded (feeds out-projection MMA)
    const int b = z >> 4, h = z & 15;
#pragma unroll
    for (int i = 0; i < 4; i++) {
        int r0 = m0 + wtm + i * 16 + g;
#pragma unroll
        for (int j = 0; j < 2; j++) {
            int c0 = wtn + j * 8 + 2 * l4;
            size_t ob = ((size_t)b * SS + r0) * DD + h * DH + c0;
            *(float2*)&ctx[ob]          = make_float2(rtf(acc[i][j][0]), rtf(acc[i][j][1]));
            *(float2*)&ctx[ob + 8 * DD] = make_float2(rtf(acc[i][j][2]), rtf(acc[i][j][3]));
        }
    }
}

// ---------------- launch -----------------------------------------------------
extern "C" void kernel_launch(void* const* d_in, const int* in_sizes, int n_in,
                              void* d_out, int out_size)
{
    (void)in_sizes; (void)n_in;
    const float* q    = (const float*)d_in[0];
    const float* k    = (const float*)d_in[1];
    const float* v    = (const float*)d_in[2];
    const float* Wq   = (const float*)d_in[3];
    const float* bq   = (const float*)d_in[4];
    const float* Wk   = (const float*)d_in[5];
    const float* bk   = (const float*)d_in[6];
    const float* Wv   = (const float*)d_in[7];
    const float* bv   = (const float*)d_in[8];
    const float* Wo   = (const float*)d_in[9];
    const float* bo   = (const float*)d_in[10];
    const float* ln_g = (const float*)d_in[11];
    const float* ln_b = (const float*)d_in[12];

    float *ln_buf, *pr_buf, *ctx_buf, *sc_buf, *wt_buf, *part_buf, *inv_buf;
    cudaGetSymbolAddress((void**)&ln_buf,   g_ln);
    cudaGetSymbolAddress((void**)&pr_buf,   g_pr);
    cudaGetSymbolAddress((void**)&ctx_buf,  g_ctx);
    cudaGetSymbolAddress((void**)&sc_buf,   g_sc);
    cudaGetSymbolAddress((void**)&wt_buf,   g_wt);
    cudaGetSymbolAddress((void**)&part_buf, g_part);
    cudaGetSymbolAddress((void**)&inv_buf,  g_inv);

    float* out = (float*)d_out;
    float* attnOut = ((size_t)out_size >= OUT_ELEMS + ATTN_ELEMS)
                        ? out + OUT_ELEMS
                        : sc_buf;   // fallback: normalize in place

    float* qn = ln_buf;
    float* kn = ln_buf + OUT_ELEMS;
    float* vn = ln_buf + 2 * OUT_ELEMS;
    float* qs = pr_buf;
    float* ks = pr_buf + OUT_ELEMS;
    float* vs = pr_buf + 2 * OUT_ELEMS;
    float* wq = wt_buf;
    float* wk = wt_buf + (size_t)DD * DD;
    float* wv = wt_buf + 2ull * DD * DD;
    float* wo = wt_buf + 3ull * DD * DD;

    cudaFuncSetAttribute(gemm2<0>, cudaFuncAttributeMaxDynamicSharedMemorySize, 4 * 128 * SA * 4);
    cudaFuncSetAttribute(gemm2<1>, cudaFuncAttributeMaxDynamicSharedMemorySize, 4 * 128 * SA * 4);
    cudaFuncSetAttribute(qk_kernel, cudaFuncAttributeMaxDynamicSharedMemorySize, 2 * 128 * SQ * 4);
    cudaFuncSetAttribute(pv_kernel, cudaFuncAttributeMaxDynamicSharedMemorySize,
                         (2 * 128 * SPA + 2 * 32 * 64 + 128) * 4);

    // 0. Pre-round weights to tf32
    int n4 = DD * DD / 4;
    roundw_kernel<<<n4 / 256, 256>>>((const float4*)Wq, (float4*)wq);
    roundw_kernel<<<n4 / 256, 256>>>((const float4*)Wk, (float4*)wk);
    roundw_kernel<<<n4 / 256, 256>>>((const float4*)Wv, (float4*)wv);
    roundw_kernel<<<n4 / 256, 256>>>((const float4*)Wo, (float4*)wo);

    // 1. LayerNorm (tf32-rounded output)
    ln_kernel<<<dim3(ROWS, 3), 256>>>(q, k, v, ln_g, ln_b, ln_buf);

    // 2. Projections
    size_t gsm = 4 * 128 * SA * 4;
    gemm2<0><<<dim3(8, 32), 256, gsm>>>(qn, wq, bq, qs, 0.125f);
    gemm2<0><<<dim3(8, 32), 256, gsm>>>(kn, wk, bk, ks, 1.0f);
    gemm2<0><<<dim3(8, 32), 256, gsm>>>(vn, wv, bv, vs, 1.0f);

    // 3. QK^T + exp + partial sums (+ zero-fill upper attn)
    qk_kernel<<<dim3(16, 16, 32), 256, 2 * 128 * SQ * 4>>>(qs, ks, sc_buf, attnOut, part_buf);

    // 4. Row sums -> reciprocals
    rowsum_kernel<<<256, 256>>>(part_buf, inv_buf);

    // 5. PV + normalize + write attn
    pv_kernel<<<dim3(16, 32), 256, (2 * 128 * SPA + 2 * 32 * 64 + 128) * 4>>>(
        sc_buf, vs, inv_buf, attnOut, ctx_buf);

    // 6. Output projection (exact output)
    gemm2<1><<<dim3(8, 32), 256, gsm>>>(ctx_buf, wo, bo, out, 1.0f);
}

// round 9
// speedup vs baseline: 1.5155x; 1.0140x over previous
#include <cuda_runtime.h>
#include <cuda_bf16.h>
#include <cstdint>
#include <cstddef>
#include <math_constants.h>

#define BB   2
#define SS   2048
#define DD   1024
#define HH   16
#define DH   64
#define BH   (BB*HH)                 // 32
#define ROWS (BB*SS)                 // 4096
#define OUT_ELEMS  ((size_t)BB*SS*DD)        // 4,194,304
#define ATTN_ELEMS ((size_t)BH*SS*SS)        // 134,217,728

// ---------------- scratch ---------------------------------------------------
__device__ float g_ln[3ull * OUT_ELEMS];     // qn,kn,vn (tf32-rounded)
__device__ float g_pr[3ull * OUT_ELEMS];     // qs,ks,vs (tf32-rounded) [BH][S][64]
__device__ float g_ctx[OUT_ELEMS];           // context [B,T,D] (tf32-rounded)
__device__ float g_sc[ATTN_ELEMS];           // exp(score) scratch (exact fp32)
__device__ float g_wt[4ull * DD * DD];       // tf32-rounded Wq,Wk,Wv,Wo
__device__ float g_part[(size_t)BH * SS * 16];   // per-block row partial sums
__device__ float g_inv[(size_t)BH * SS];         // 1/rowsum

// ---------------- helpers ---------------------------------------------------
__device__ __forceinline__ uint32_t f2tf32(float x) {
    uint32_t r;
    asm("cvt.rna.tf32.f32 %0, %1;" : "=r"(r) : "f"(x));
    return r;
}
__device__ __forceinline__ float rtf(float x) { return __uint_as_float(f2tf32(x)); }

__device__ __forceinline__ void mma_tf32(float* c, const uint32_t* a, const uint32_t* b) {
    asm volatile(
        "mma.sync.aligned.m16n8k8.row.col.f32.tf32.tf32.f32 "
        "{%0,%1,%2,%3},{%4,%5,%6,%7},{%8,%9},{%0,%1,%2,%3};"
        : "+f"(c[0]), "+f"(c[1]), "+f"(c[2]), "+f"(c[3])
        : "r"(a[0]), "r"(a[1]), "r"(a[2]), "r"(a[3]), "r"(b[0]), "r"(b[1]));
}

#define CP16(dst_u32, src_ptr) \
    asm volatile("cp.async.cg.shared.global [%0], [%1], 16;\n" :: "r"(dst_u32), "l"(src_ptr))
#define CPCOMMIT() asm volatile("cp.async.commit_group;\n" ::)
#define CPWAIT(n)  asm volatile("cp.async.wait_group %0;\n" :: "n"(n))

template <bool ISMAX>
__device__ __forceinline__ float block_reduce(float v) {
    __shared__ float sm[8];
    int tid = threadIdx.x;
#pragma unroll
    for (int o = 16; o; o >>= 1) {
        float other = __shfl_xor_sync(0xffffffffu, v, o);
        v = ISMAX ? fmaxf(v, other) : (v + other);
    }
    if ((tid & 31) == 0) sm[tid >> 5] = v;
    __syncthreads();
    if (tid < 32) {
        float r = (tid < 8) ? sm[tid] : (ISMAX ? -CUDART_INF_F : 0.0f);
#pragma unroll
        for (int o = 4; o; o >>= 1) {
            float other = __shfl_xor_sync(0xffffffffu, r, o);
            r = ISMAX ? fmaxf(r, other) : (r + other);
        }
        if (tid == 0) sm[0] = r;
    }
    __syncthreads();
    float res = sm[0];
    __syncthreads();
    return res;
}

// ---------------- kernel 0: round all 4 weight matrices to tf32 -------------
__global__ __launch_bounds__(256) void roundw4_kernel(
    const float4* __restrict__ s0, const float4* __restrict__ s1,
    const float4* __restrict__ s2, const float4* __restrict__ s3,
    float4* __restrict__ out)
{
    int idx = blockIdx.x * 256 + threadIdx.x;       // 4 * 262144 float4
    int w = idx >> 18;                               // 262144 float4 per matrix
    const float4* s = (w == 0) ? s0 : (w == 1) ? s1 : (w == 2) ? s2 : s3;
    float4 v = s[idx & 0x3FFFF];
    v.x = rtf(v.x); v.y = rtf(v.y); v.z = rtf(v.z); v.w = rtf(v.w);
    out[idx] = v;
}

// ---------------- kernel 1: LayerNorm (tf32-rounded output) -----------------
__global__ __launch_bounds__(256) void ln_kernel(
    const float* __restrict__ q, const float* __restrict__ k,
    const float* __restrict__ v, const float* __restrict__ gg,
    const float* __restrict__ bb, float* __restrict__ out)
{
    int row = blockIdx.x;
    int which = blockIdx.y;
    const float* x = (which == 0 ? q : (which == 1 ? k : v)) + (size_t)row * DD;
    float* o = out + (size_t)which * OUT_ELEMS + (size_t)row * DD;
    int tid = threadIdx.x;

    float4 xv = reinterpret_cast<const float4*>(x)[tid];
    float s = xv.x + xv.y + xv.z + xv.w;
    float mean = block_reduce<false>(s) * (1.0f / DD);
    float d0 = xv.x - mean, d1 = xv.y - mean, d2 = xv.z - mean, d3 = xv.w - mean;
    float ss = d0 * d0 + d1 * d1 + d2 * d2 + d3 * d3;
    float var = block_reduce<false>(ss) * (1.0f / DD);
    float rstd = rsqrtf(var + 1e-5f);

    float4 gv = reinterpret_cast<const float4*>(gg)[tid];
    float4 bv = reinterpret_cast<const float4*>(bb)[tid];
    float4 ov;
    ov.x = rtf(d0 * rstd * gv.x + bv.x);
    ov.y = rtf(d1 * rstd * gv.y + bv.y);
    ov.z = rtf(d2 * rstd * gv.z + bv.z);
    ov.w = rtf(d3 * rstd * gv.w + bv.w);
    reinterpret_cast<float4*>(o)[tid] = ov;
}

// ---------------- kernel 2: 128x128x32 tf32 GEMM, cp.async, 1 sync/chunk ----
// blockIdx.z batches independent GEMMs (A/B/bias/C strided by z).
// EPI 0: proj scatter to [BH,S,64], tf32-rounded; z=0 scaled by scale0.
// EPI 1: plain C[m*1024+n] = acc + bias[n] (exact, final output), z=0 only.
#define SA 40
template <int EPI>
__global__ __launch_bounds__(256, 2) void gemm2(
    const float* __restrict__ A0, const float* __restrict__ B0,
    const float* __restrict__ b0, const float* __restrict__ b1,
    const float* __restrict__ b2, float* __restrict__ C0, float scale0)
{
    extern __shared__ float smd[];
    float* As = smd;              // 2 x 128*40
    float* Bs = smd + 2 * 128 * SA;

    const int z = blockIdx.z;
    const float* A    = A0 + (size_t)z * OUT_ELEMS;
    const float* Bm   = B0 + (size_t)z * DD * DD;
    const float* bias = (z == 0) ? b0 : (z == 1) ? b1 : b2;
    float* C          = C0 + (size_t)z * OUT_ELEMS;
    const float scale = (EPI == 0 && z == 0) ? scale0 : 1.0f;

    const int m0 = blockIdx.y * 128, n0 = blockIdx.x * 128;
    const int tid = threadIdx.x, lane = tid & 31, warp = tid >> 5;
    const int g = lane >> 2, l4 = lane & 3;
    const int wtm = (warp & 1) * 64, wtn = (warp >> 1) * 32;

    float acc[4][4][4];
#pragma unroll
    for (int i = 0; i < 4; i++)
#pragma unroll
        for (int j = 0; j < 4; j++)
#pragma unroll
            for (int e = 0; e < 4; e++) acc[i][j][e] = 0.0f;

    const int ar = tid >> 3;            // 0..31
    const int ac = (tid & 7) * 4;       // 0..28
    uint32_t sAu = (uint32_t)__cvta_generic_to_shared(As);
    uint32_t sBu = (uint32_t)__cvta_generic_to_shared(Bs);

    auto stage = [&](int chunk, int buf) {
        const float* Ap = A + (size_t)m0 * 1024 + chunk * 32;
        const float* Bp = Bm + (size_t)n0 * 1024 + chunk * 32;
        uint32_t da = sAu + (uint32_t)(buf * 128 * SA) * 4;
        uint32_t db = sBu + (uint32_t)(buf * 128 * SA) * 4;
#pragma unroll
        for (int i = 0; i < 4; i++) {
            int r = ar + i * 32;
            CP16(da + (uint32_t)(r * SA + ac) * 4, Ap + (size_t)r * 1024 + ac);
            CP16(db + (uint32_t)(r * SA + ac) * 4, Bp + (size_t)r * 1024 + ac);
        }
    };

    auto domma = [&](int buf) {
        const float* Ab = As + buf * 128 * SA;
        const float* Bb = Bs + buf * 128 * SA;
#pragma unroll
        for (int kk = 0; kk < 32; kk += 8) {
            int kc = kk + 2 * l4;
            uint32_t af[4][4], bf[4][2];
#pragma unroll
            for (int i = 0; i < 4; i++) {
                int r = wtm + i * 16 + g;
                uint2 p0 = *(const uint2*)&Ab[r * SA + kc];
                uint2 p1 = *(const uint2*)&Ab[(r + 8) * SA + kc];
                af[i][0] = p0.x; af[i][2] = p0.y;
                af[i][1] = p1.x; af[i][3] = p1.y;
            }
#pragma unroll
            for (int j = 0; j < 4; j++) {
                int cN = wtn + j * 8 + g;
                uint2 p = *(const uint2*)&Bb[cN * SA + kc];
                bf[j][0] = p.x; bf[j][1] = p.y;
            }
#pragma unroll
            for (int i = 0; i < 4; i++)
#pragma unroll
                for (int j = 0; j < 4; j++)
                    mma_tf32(acc[i][j], af[i], bf[j]);
        }
    };

    // double buffer, ONE barrier per chunk:
    // top-of-iter sync => (a) stage-c data visible to all warps,
    // (b) all warps done reading buf from iter c-1, so staging c+1 into buf^1
    // (the buffer read in iter c-1) is safe.
    stage(0, 0); CPCOMMIT();
    int buf = 0;
    for (int c = 0; c < 32; c++) {
        CPWAIT(0);
        __syncthreads();
        if (c + 1 < 32) { stage(c + 1, buf ^ 1); CPCOMMIT(); }
        domma(buf);
        buf ^= 1;
    }

#pragma unroll
    for (int i = 0; i < 4; i++) {
        int m = m0 + wtm + i * 16 + g;
#pragma unroll
        for (int j = 0; j < 4; j++) {
            int n = n0 + wtn + j * 8 + 2 * l4;
            float2 bv = *(const float2*)&bias[n];
            float v0 = (acc[i][j][0] + bv.x) * scale;
            float v1 = (acc[i][j][1] + bv.y) * scale;
            float v2 = (acc[i][j][2] + bv.x) * scale;
            float v3 = (acc[i][j][3] + bv.y) * scale;
            if (EPI == 0) {
                v0 = rtf(v0); v1 = rtf(v1); v2 = rtf(v2); v3 = rtf(v3);
                int h = n >> 6, d = n & 63;
                size_t base0 = (((size_t)(m >> 11) * HH + h) * SS + (m & 2047)) * DH + d;
                size_t base1 = (((size_t)((m + 8) >> 11) * HH + h) * SS + ((m + 8) & 2047)) * DH + d;
                *(float2*)&C[base0] = make_float2(v0, v1);
                *(float2*)&C[base1] = make_float2(v2, v3);
            } else {
                *(float2*)&C[(size_t)m * DD + n] = make_float2(v0, v1);
                *(float2*)&C[(size_t)(m + 8) * DD + n] = make_float2(v2, v3);
            }
        }
    }
}

// ---------------- kernel 3: QK^T + exp + partial row sums -------------------
#define SQ 72
__global__ __launch_bounds__(256, 2) void qk_kernel(
    const float* __restrict__ Q, const float* __restrict__ Kt,
    float* __restrict__ scratch, float* __restrict__ attnOut,
    float* __restrict__ part)
{
    const int n0 = blockIdx.x * 128, m0 = blockIdx.y * 128, z = blockIdx.z;
    const long zo = (long)z * SS;
    const int tid = threadIdx.x;

    if (n0 > m0) {                       // strictly above diagonal: zeros
        float4 zz = make_float4(0.f, 0.f, 0.f, 0.f);
#pragma unroll
        for (int t = 0; t < 16; t++) {
            int idx = tid + t * 256;
            int r = idx >> 5, c = (idx & 31) * 4;
            *(float4*)&attnOut[(zo + m0 + r) * SS + n0 + c] = zz;
        }
        return;
    }

    extern __shared__ float smd[];
    float* As = smd;                 // 128*72
    float* Bs = smd + 128 * SQ;

    const int lane = tid & 31, warp = tid >> 5;
    const int g = lane >> 2, l4 = lane & 3;
    const int wtm = (warp & 1) * 64, wtn = (warp >> 1) * 32, wn = warp >> 1;

#pragma unroll
    for (int t = 0; t < 8; t++) {
        int idx = tid + t * 256;
        int r = idx >> 4, c = (idx & 15) * 4;
        *(float4*)&As[r * SQ + c] = *(const float4*)&Q[(zo + m0 + r) * DH + c];
        *(float4*)&Bs[r * SQ + c] = *(const float4*)&Kt[(zo + n0 + r) * DH + c];
    }
    __syncthreads();

    float acc[4][4][4];
#pragma unroll
    for (int i = 0; i < 4; i++)
#pragma unroll
        for (int j = 0; j < 4; j++)
#pragma unroll
            for (int e = 0; e < 4; e++) acc[i][j][e] = 0.0f;

#pragma unroll
    for (int kk = 0; kk < 64; kk += 8) {
        int kc = kk + 2 * l4;
        uint32_t af[4][4], bf[4][2];
#pragma unroll
        for (int i = 0; i < 4; i++) {
            int r = wtm + i * 16 + g;
            uint2 p0 = *(const uint2*)&As[r * SQ + kc];
            uint2 p1 = *(const uint2*)&As[(r + 8) * SQ + kc];
            af[i][0] = p0.x; af[i][2] = p0.y;
            af[i][1] = p1.x; af[i][3] = p1.y;
        }
#pragma unroll
        for (int j = 0; j < 4; j++) {
            int cN = wtn + j * 8 + g;
            uint2 p = *(const uint2*)&Bs[cN * SQ + kc];
            bf[j][0] = p.x; bf[j][1] = p.y;
        }
#pragma unroll
        for (int i = 0; i < 4; i++)
#pragma unroll
            for (int j = 0; j < 4; j++)
                mma_tf32(acc[i][j], af[i], bf[j]);
    }

    // epilogue: exp + mask + store + partial row sums
    float rs[4][2];
#pragma unroll
    for (int i = 0; i < 4; i++) { rs[i][0] = 0.f; rs[i][1] = 0.f; }

#pragma unroll
    for (int i = 0; i < 4; i++) {
        int r0 = m0 + wtm + i * 16 + g;
#pragma unroll
        for (int j = 0; j < 4; j++) {
            int c0 = n0 + wtn + j * 8 + 2 * l4;
            float e0 = (c0     <= r0    ) ? __expf(acc[i][j][0]) : 0.f;
            float e1 = (c0 + 1 <= r0    ) ? __expf(acc[i][j][1]) : 0.f;
            float e2 = (c0     <= r0 + 8) ? __expf(acc[i][j][2]) : 0.f;
            float e3 = (c0 + 1 <= r0 + 8) ? __expf(acc[i][j][3]) : 0.f;
            *(float2*)&scratch[(zo + r0) * SS + c0]       = make_float2(e0, e1);
            *(float2*)&scratch[(zo + r0 + 8) * SS + c0]   = make_float2(e2, e3);
            rs[i][0] += e0 + e1;
            rs[i][1] += e2 + e3;
        }
    }
#pragma unroll
    for (int i = 0; i < 4; i++)
#pragma unroll
        for (int h = 0; h < 2; h++) {
            float v = rs[i][h];
            v += __shfl_xor_sync(0xffffffffu, v, 1);
            v += __shfl_xor_sync(0xffffffffu, v, 2);
            rs[i][h] = v;
        }
    __syncthreads();
    float* red = smd;                // [128][4]
    if (l4 == 0) {
#pragma unroll
        for (int i = 0; i < 4; i++) {
            red[(wtm + i * 16 + g) * 4 + wn]     = rs[i][0];
            red[(wtm + i * 16 + g + 8) * 4 + wn] = rs[i][1];
        }
    }
    __syncthreads();
    if (tid < 128) {
        float s = red[tid * 4] + red[tid * 4 + 1] + red[tid * 4 + 2] + red[tid * 4 + 3];
        part[(zo + m0 + tid) * 16 + (n0 >> 7)] = s;
    }
}

// ---------------- kernel 4: row-sum reduce -> reciprocal --------------------
__global__ __launch_bounds__(256) void rowsum_kernel(
    const float* __restrict__ part, float* __restrict__ inv)
{
    int idx = blockIdx.x * 256 + threadIdx.x;    // < 65536
    int t = idx & (SS - 1);
    int nb = (t >> 7) + 1;
    float s = 0.f;
    for (int b = 0; b < nb; b++) s += part[(size_t)idx * 16 + b];
    inv[idx] = 1.0f / s;
}

// ---------------- kernel 5: PV GEMM, normalize + write attn -----------------
// m-blocks processed in REVERSE (largest causal extent first) for wave balance.
#define SPA 40
__global__ __launch_bounds__(256, 2) void pv_kernel(
    float* __restrict__ scratch, const float* __restrict__ V,
    const float* __restrict__ inv, float* __restrict__ attnOut,
    float* __restrict__ ctx)
{
    const int m0 = (15 - blockIdx.x) * 128, z = blockIdx.y;
    const long zo = (long)z * SS;
    const int tid = threadIdx.x, lane = tid & 31, warp = tid >> 5;
    const int g = lane >> 2, l4 = lane & 3;
    const int wtm = (warp & 1) * 64, wtn = (warp >> 1) * 16;

    extern __shared__ float smd[];
    float* As = smd;                           // 2 x 128*40
    float* Bs = smd + 2 * 128 * SPA;           // 2 x 32*64
    float* invs = Bs + 2 * 32 * 64;            // 128

    if (tid < 128) invs[tid] = inv[zo + m0 + tid];
    __syncthreads();

    float acc[4][2][4];
#pragma unroll
    for (int i = 0; i < 4; i++)
#pragma unroll
        for (int j = 0; j < 2; j++)
#pragma unroll
            for (int e = 0; e < 4; e++) acc[i][j][e] = 0.0f;

    const int NC = (m0 >> 5) + 4;

    float4 pa[4]; float4 pb[2];
    int arr[4], acl[4];
#pragma unroll
    for (int t = 0; t < 4; t++) { int idx = tid + t * 256; arr[t] = idx >> 3; acl[t] = (idx & 7) * 4; }
    int bkr[2], bnc[2];
#pragma unroll
    for (int t = 0; t < 2; t++) { int idx = tid + t * 256; bkr[t] = idx >> 4; bnc[t] = (idx & 15) * 4; }

    auto loadc = [&](int c) {
        int k0 = c * 32;
#pragma unroll
        for (int t = 0; t < 4; t++)
            pa[t] = *(const float4*)&scratch[(zo + m0 + arr[t]) * SS + k0 + acl[t]];
#pragma unroll
        for (int t = 0; t < 2; t++)
            pb[t] = *(const float4*)&V[(zo + k0 + bkr[t]) * DH + bnc[t]];
    };

    loadc(0);
    for (int c = 0; c < NC; c++) {
        int buf = c & 1;
        float* Ab = As + buf * 128 * SPA;
        float* Bb = Bs + buf * 32 * 64;
        int k0 = c * 32;
        // normalize: exact -> attn output, tf32-rounded -> smem MMA operand
#pragma unroll
        for (int t = 0; t < 4; t++) {
            float iv = invs[arr[t]];
            float4 v = pa[t];
            v.x *= iv; v.y *= iv; v.z *= iv; v.w *= iv;
            *(float4*)&attnOut[(zo + m0 + arr[t]) * SS + k0 + acl[t]] = v;
            float4 vr;
            vr.x = rtf(v.x); vr.y = rtf(v.y); vr.z = rtf(v.z); vr.w = rtf(v.w);
            *(float4*)&Ab[arr[t] * SPA + acl[t]] = vr;
        }
#pragma unroll
        for (int t = 0; t < 2; t++) {
            int cp = (bnc[t] + 4 * bkr[t]) & 63;      // rotate-4 swizzle
            *(float4*)&Bb[bkr[t] * 64 + cp] = pb[t];  // V pre-rounded
        }
        __syncthreads();
        if (c + 1 < NC) loadc(c + 1);
#pragma unroll
        for (int kk = 0; kk < 32; kk += 8) {
            int kc = kk + 2 * l4;
            uint32_t af[4][4], bf[2][2];
#pragma unroll
            for (int i = 0; i < 4; i++) {
                int r = wtm + i * 16 + g;
                uint2 p0 = *(const uint2*)&Ab[r * SPA + kc];
                uint2 p1 = *(const uint2*)&Ab[(r + 8) * SPA + kc];
                af[i][0] = p0.x; af[i][2] = p0.y;
                af[i][1] = p1.x; af[i][3] = p1.y;
            }
#pragma unroll
            for (int j = 0; j < 2; j++) {
                int cN = wtn + j * 8 + g;
                bf[j][0] = __float_as_uint(Bb[kc * 64 + ((cN + 4 * kc) & 63)]);
                bf[j][1] = __float_as_uint(Bb[(kc + 1) * 64 + ((cN + 4 * (kc + 1)) & 63)]);
            }
#pragma unroll
            for (int i = 0; i < 4; i++)
#pragma unroll
                for (int j = 0; j < 2; j++)
                    mma_tf32(acc[i][j], af[i], bf[j]);
        }
        __syncthreads();
    }

    // epilogue -> ctx [B,T,D], tf32-rounded (feeds out-projection MMA)
    const int b = z >> 4, h = z & 15;
#pragma unroll
    for (int i = 0; i < 4; i++) {
        int r0 = m0 + wtm + i * 16 + g;
#pragma unroll
        for (int j = 0; j < 2; j++) {
            int c0 = wtn + j * 8 + 2 * l4;
            size_t ob = ((size_t)b * SS + r0) * DD + h * DH + c0;
            *(float2*)&ctx[ob]          = make_float2(rtf(acc[i][j][0]), rtf(acc[i][j][1]));
            *(float2*)&ctx[ob + 8 * DD] = make_float2(rtf(acc[i][j][2]), rtf(acc[i][j][3]));
        }
    }
}

// ---------------- launch -----------------------------------------------------
extern "C" void kernel_launch(void* const* d_in, const int* in_sizes, int n_in,
                              void* d_out, int out_size)
{
    (void)in_sizes; (void)n_in;
    const float* q    = (const float*)d_in[0];
    const float* k    = (const float*)d_in[1];
    const float* v    = (const float*)d_in[2];
    const float* Wq   = (const float*)d_in[3];
    const float* bq   = (const float*)d_in[4];
    const float* Wk   = (const float*)d_in[5];
    const float* bk   = (const float*)d_in[6];
    const float* Wv   = (const float*)d_in[7];
    const float* bv   = (const float*)d_in[8];
    const float* Wo   = (const float*)d_in[9];
    const float* bo   = (const float*)d_in[10];
    const float* ln_g = (const float*)d_in[11];
    const float* ln_b = (const float*)d_in[12];

    float *ln_buf, *pr_buf, *ctx_buf, *sc_buf, *wt_buf, *part_buf, *inv_buf;
    cudaGetSymbolAddress((void**)&ln_buf,   g_ln);
    cudaGetSymbolAddress((void**)&pr_buf,   g_pr);
    cudaGetSymbolAddress((void**)&ctx_buf,  g_ctx);
    cudaGetSymbolAddress((void**)&sc_buf,   g_sc);
    cudaGetSymbolAddress((void**)&wt_buf,   g_wt);
    cudaGetSymbolAddress((void**)&part_buf, g_part);
    cudaGetSymbolAddress((void**)&inv_buf,  g_inv);

    float* out = (float*)d_out;
    float* attnOut = ((size_t)out_size >= OUT_ELEMS + ATTN_ELEMS)
                        ? out + OUT_ELEMS
                        : sc_buf;   // fallback: normalize in place

    float* wo = wt_buf + 3ull * DD * DD;

    cudaFuncSetAttribute(gemm2<0>, cudaFuncAttributeMaxDynamicSharedMemorySize, 4 * 128 * SA * 4);
    cudaFuncSetAttribute(gemm2<1>, cudaFuncAttributeMaxDynamicSharedMemorySize, 4 * 128 * SA * 4);
    cudaFuncSetAttribute(qk_kernel, cudaFuncAttributeMaxDynamicSharedMemorySize, 2 * 128 * SQ * 4);
    cudaFuncSetAttribute(pv_kernel, cudaFuncAttributeMaxDynamicSharedMemorySize,
                         (2 * 128 * SPA + 2 * 32 * 64 + 128) * 4);

    // 0. Pre-round all 4 weight matrices to tf32 (one launch)
    roundw4_kernel<<<4096, 256>>>((const float4*)Wq, (const float4*)Wk,
                                  (const float4*)Wv, (const float4*)Wo,
                                  (float4*)wt_buf);

    // 1. LayerNorm (tf32-rounded output)
    ln_kernel<<<dim3(ROWS, 3), 256>>>(q, k, v, ln_g, ln_b, ln_buf);

    // 2. All 3 projections in ONE launch (z = q/k/v)
    size_t gsm = 4 * 128 * SA * 4;
    gemm2<0><<<dim3(8, 32, 3), 256, gsm>>>(ln_buf, wt_buf, bq, bk, bv, pr_buf, 0.125f);

    // 3. QK^T + exp + partial sums (+ zero-fill upper attn)
    float* qs = pr_buf;
    float* ks = pr_buf + OUT_ELEMS;
    float* vs = pr_buf + 2 * OUT_ELEMS;
    qk_kernel<<<dim3(16, 16, 32), 256, 2 * 128 * SQ * 4>>>(qs, ks, sc_buf, attnOut, part_buf);

    // 4. Row sums -> reciprocals
    rowsum_kernel<<<256, 256>>>(part_buf, inv_buf);

    // 5. PV + normalize + write attn (reverse block order)
    pv_kernel<<<dim3(16, 32), 256, (2 * 128 * SPA + 2 * 32 * 64 + 128) * 4>>>(
        sc_buf, vs, inv_buf, attnOut, ctx_buf);

    // 6. Output projection (exact output)
    gemm2<1><<<dim3(8, 32, 1), 256, gsm>>>(ctx_buf, wo, bo, bo, bo, out, 1.0f);
}